// round 1
// baseline (speedup 1.0000x reference)
#include <cuda_runtime.h>
#include <math.h>

#define NN 100000
#define EE 3200000
#define FF 128

// ---------------- static device scratch (no allocations allowed) ----------------
__device__ float g_xs[NN * FF];     // scaled features (gather source)
__device__ float g_agg[NN * FF];    // aggregation result
__device__ float g_h[NN * FF];      // hidden activations
__device__ float g_outnorm[NN];
__device__ float g_innorm[NN];
__device__ int   g_outdeg[NN];
__device__ int   g_indeg[NN];
__device__ int   g_rowptr[NN + 1];
__device__ int   g_cursor[NN];
__device__ int   g_csrc[EE];        // CSR (by dst) column indices = src nodes

// ---------------- graph preprocessing ----------------
__global__ void zero_kernel() {
    int i = blockIdx.x * blockDim.x + threadIdx.x;
    if (i < NN) { g_outdeg[i] = 0; g_indeg[i] = 0; g_cursor[i] = 0; }
}

__global__ void degree_kernel(const int* __restrict__ src, const int* __restrict__ dst) {
    int e = blockIdx.x * blockDim.x + threadIdx.x;
    if (e < EE) {
        atomicAdd(&g_outdeg[src[e]], 1);
        atomicAdd(&g_indeg[dst[e]], 1);
    }
}

__global__ void norm_kernel() {
    int i = blockIdx.x * blockDim.x + threadIdx.x;
    if (i < NN) {
        g_outnorm[i] = rsqrtf((float)max(g_outdeg[i], 1));
        g_innorm[i]  = rsqrtf((float)max(g_indeg[i], 1));
    }
}

// single-block exclusive scan of g_indeg -> g_rowptr
__global__ void scan_kernel() {
    __shared__ int sums[1024];
    int tid = threadIdx.x;
    const int per = (NN + 1023) / 1024;  // 98
    int start = tid * per;
    int end = min(start + per, NN);
    int s = 0;
    for (int i = start; i < end; i++) s += g_indeg[i];
    sums[tid] = s;
    __syncthreads();
    for (int off = 1; off < 1024; off <<= 1) {
        int v = 0;
        if (tid >= off) v = sums[tid - off];
        __syncthreads();
        sums[tid] += v;
        __syncthreads();
    }
    int run = sums[tid] - s;  // exclusive prefix
    for (int i = start; i < end; i++) { g_rowptr[i] = run; run += g_indeg[i]; }
    if (start < NN && end == NN) g_rowptr[NN] = run;
}

__global__ void fill_kernel(const int* __restrict__ src, const int* __restrict__ dst) {
    int e = blockIdx.x * blockDim.x + threadIdx.x;
    if (e < EE) {
        int d = dst[e];
        int pos = atomicAdd(&g_cursor[d], 1);
        g_csrc[g_rowptr[d] + pos] = src[e];
    }
}

// ---------------- feature scaling: xs = x * out_norm[row] ----------------
__global__ void scale_kernel(const float* __restrict__ x) {
    int i = blockIdx.x * blockDim.x + threadIdx.x;  // over NN*32 float4s
    if (i < NN * 32) {
        int node = i >> 5;
        float s = g_outnorm[node];
        float4 v = ((const float4*)x)[i];
        v.x *= s; v.y *= s; v.z *= s; v.w *= s;
        ((float4*)g_xs)[i] = v;
    }
}

// ---------------- aggregation: one warp per node, register accumulation ----------------
__global__ void agg_kernel() {
    int w = (blockIdx.x * blockDim.x + threadIdx.x) >> 5;
    if (w >= NN) return;
    int lane = threadIdx.x & 31;
    int s = g_rowptr[w], e = g_rowptr[w + 1];
    const float4* __restrict__ X = (const float4*)g_xs;
    float4 acc = make_float4(0.f, 0.f, 0.f, 0.f);
    int j = s;
    for (; j + 3 < e; j += 4) {
        int u0 = g_csrc[j], u1 = g_csrc[j + 1], u2 = g_csrc[j + 2], u3 = g_csrc[j + 3];
        float4 a = X[u0 * 32 + lane];
        float4 b = X[u1 * 32 + lane];
        float4 c = X[u2 * 32 + lane];
        float4 d = X[u3 * 32 + lane];
        acc.x += a.x + b.x + c.x + d.x;
        acc.y += a.y + b.y + c.y + d.y;
        acc.z += a.z + b.z + c.z + d.z;
        acc.w += a.w + b.w + c.w + d.w;
    }
    for (; j < e; j++) {
        int u = g_csrc[j];
        float4 a = X[u * 32 + lane];
        acc.x += a.x; acc.y += a.y; acc.z += a.z; acc.w += a.w;
    }
    ((float4*)g_agg)[w * 32 + lane] = acc;
}

// ---------------- fused GEMM: out = act((prescale[r]*A) @ W + b) * postscale[r] ----------------
// A: [M,128] row-major, W: [128,BN] row-major. MODE: 0 = relu, 2 = sigmoid.
template <int BN, int MODE>
__global__ void __launch_bounds__(256) gemm_kernel(
    const float* __restrict__ A, const float* __restrict__ W,
    const float* __restrict__ bias,
    const float* __restrict__ prescale, const float* __restrict__ postscale,
    float* __restrict__ out, int M)
{
    constexpr int BM = 64, K = 128, BK = 32;
    constexpr int TM = 4;
    constexpr int TN = (BM * BN) / (256 * TM);  // 8 (BN=128) or 4 (BN=64)
    __shared__ float As[BK][BM + 4];  // transposed A chunk
    __shared__ float Ws[BK][BN];

    int tid = threadIdx.x;
    int tx = tid & 15, ty = tid >> 4;
    int brow = blockIdx.x * BM;

    float acc[TM][TN];
#pragma unroll
    for (int i = 0; i < TM; i++)
#pragma unroll
        for (int j = 0; j < TN; j++) acc[i][j] = 0.f;

    for (int k0 = 0; k0 < K; k0 += BK) {
        // load A chunk (BM x BK), transposed into smem
#pragma unroll
        for (int i = tid; i < BM * BK / 4; i += 256) {
            int r = i >> 3;          // / (BK/4)
            int kq = i & 7;
            int gr = brow + r;
            float4 v = (gr < M) ? *(const float4*)(A + (size_t)gr * K + k0 + kq * 4)
                                : make_float4(0.f, 0.f, 0.f, 0.f);
            As[kq * 4 + 0][r] = v.x;
            As[kq * 4 + 1][r] = v.y;
            As[kq * 4 + 2][r] = v.z;
            As[kq * 4 + 3][r] = v.w;
        }
        // load W chunk (BK x BN)
#pragma unroll
        for (int i = tid; i < BK * BN / 4; i += 256) {
            int kk = i / (BN / 4);
            int cq = i % (BN / 4);
            *(float4*)&Ws[kk][cq * 4] = *(const float4*)(W + (size_t)(k0 + kk) * BN + cq * 4);
        }
        __syncthreads();
#pragma unroll
        for (int k = 0; k < BK; k++) {
            float4 a4 = *(const float4*)&As[k][ty * TM];
            float a[TM] = {a4.x, a4.y, a4.z, a4.w};
            float b[TN];
#pragma unroll
            for (int j = 0; j < TN; j += 4) {
                float4 b4 = *(const float4*)&Ws[k][tx * TN + j];
                b[j] = b4.x; b[j + 1] = b4.y; b[j + 2] = b4.z; b[j + 3] = b4.w;
            }
#pragma unroll
            for (int i = 0; i < TM; i++)
#pragma unroll
                for (int j = 0; j < TN; j++)
                    acc[i][j] = fmaf(a[i], b[j], acc[i][j]);
        }
        __syncthreads();
    }

    // epilogue
#pragma unroll
    for (int i = 0; i < TM; i++) {
        int r = brow + ty * TM + i;
        if (r < M) {
            float ps = prescale ? prescale[r] : 1.f;
            float posts = postscale ? postscale[r] : 1.f;
            float o[TN];
#pragma unroll
            for (int j = 0; j < TN; j++) {
                float v = acc[i][j] * ps + bias[tx * TN + j];
                if (MODE == 2) {
                    v = 1.f / (1.f + __expf(-v));
                } else {
                    v = fmaxf(v, 0.f) * posts;
                }
                o[j] = v;
            }
#pragma unroll
            for (int j = 0; j < TN; j += 4) {
                float4 v4 = make_float4(o[j], o[j + 1], o[j + 2], o[j + 3]);
                *(float4*)(out + (size_t)r * BN + tx * TN + j) = v4;
            }
        }
    }
}

// ---------------- launch ----------------
extern "C" void kernel_launch(void* const* d_in, const int* in_sizes, int n_in,
                              void* d_out, int out_size) {
    const float* x   = (const float*)d_in[0];
    const int*   src = (const int*)d_in[1];
    const int*   dst = (const int*)d_in[2];
    const float* W1  = (const float*)d_in[3];
    const float* b1  = (const float*)d_in[4];
    const float* W2  = (const float*)d_in[5];
    const float* b2  = (const float*)d_in[6];
    const float* Wm1 = (const float*)d_in[7];
    const float* bm1 = (const float*)d_in[8];
    const float* Wm2 = (const float*)d_in[9];
    const float* bm2 = (const float*)d_in[10];
    float* out = (float*)d_out;

    void *p_xs, *p_agg, *p_h, *p_outnorm, *p_innorm;
    cudaGetSymbolAddress(&p_xs, g_xs);
    cudaGetSymbolAddress(&p_agg, g_agg);
    cudaGetSymbolAddress(&p_h, g_h);
    cudaGetSymbolAddress(&p_outnorm, g_outnorm);
    cudaGetSymbolAddress(&p_innorm, g_innorm);

    const int TB = 256;
    int nblk = (NN + TB - 1) / TB;
    int eblk = (EE + TB - 1) / TB;

    // graph preprocessing: degrees, norms, CSR-by-dst
    zero_kernel<<<nblk, TB>>>();
    degree_kernel<<<eblk, TB>>>(src, dst);
    norm_kernel<<<nblk, TB>>>();
    scan_kernel<<<1, 1024>>>();
    fill_kernel<<<eblk, TB>>>(src, dst);

    // conv1
    scale_kernel<<<(NN * 32 + TB - 1) / TB, TB>>>(x);
    agg_kernel<<<(NN * 32 + TB - 1) / TB, TB>>>();
    // h1 = relu((agg * in_norm) @ W1 + b1); stage h1*out_norm for conv2 gather
    gemm_kernel<128, 0><<<(NN + 63) / 64, 256>>>(
        (const float*)p_agg, W1, b1, (const float*)p_innorm, (const float*)p_outnorm,
        (float*)p_xs, NN);

    // conv2
    agg_kernel<<<(NN * 32 + TB - 1) / TB, TB>>>();
    gemm_kernel<128, 0><<<(NN + 63) / 64, 256>>>(
        (const float*)p_agg, W2, b2, (const float*)p_innorm, nullptr,
        (float*)p_h, NN);

    // MLP head
    gemm_kernel<128, 0><<<(NN + 63) / 64, 256>>>(
        (const float*)p_h, Wm1, bm1, nullptr, nullptr, (float*)p_xs, NN);
    gemm_kernel<64, 2><<<(NN + 63) / 64, 256>>>(
        (const float*)p_xs, Wm2, bm2, nullptr, nullptr, out, NN);
}

// round 4
// speedup vs baseline: 1.3325x; 1.3325x over previous
#include <cuda_runtime.h>
#include <math.h>

#define NN 100000
#define EE 3200000
#define FF 128

// ---------------- static device scratch (no allocations allowed) ----------------
__device__ float g_xs[NN * FF];     // scaled features (gather source for conv2)
__device__ float g_agg[NN * FF];    // aggregation result
__device__ float g_h[NN * FF];      // hidden activations
__device__ float g_outnorm[NN];
__device__ float g_innorm[NN];
__device__ int   g_outdeg[NN];
__device__ int   g_indeg[NN];
__device__ int   g_rowptr[NN + 1];
__device__ int   g_cursor[NN];
__device__ int   g_partial[128];
__device__ int   g_csrc[EE];        // CSR (by dst) column indices = src nodes

// ---------------- f32x2 packed helpers ----------------
__device__ __forceinline__ unsigned long long pack2_dup(float x) {
    unsigned long long r;
    asm("mov.b64 %0, {%1, %1};" : "=l"(r) : "r"(__float_as_uint(x)));
    return r;
}
__device__ __forceinline__ void fma2(unsigned long long& d, unsigned long long a, unsigned long long b) {
    asm("fma.rn.f32x2 %0, %1, %2, %0;" : "+l"(d) : "l"(a), "l"(b));
}
__device__ __forceinline__ float2 unpack2(unsigned long long v) {
    unsigned int lo, hi;
    asm("mov.b64 {%0, %1}, %2;" : "=r"(lo), "=r"(hi) : "l"(v));
    float2 r; r.x = __uint_as_float(lo); r.y = __uint_as_float(hi);
    return r;
}

// ---------------- graph preprocessing ----------------
__global__ void __launch_bounds__(256) zero_kernel() {
    int i = blockIdx.x * blockDim.x + threadIdx.x;
    if (i < NN) { g_outdeg[i] = 0; g_indeg[i] = 0; g_cursor[i] = 0; }
}

__global__ void __launch_bounds__(256) degree_kernel(const int* __restrict__ src, const int* __restrict__ dst) {
    int e = blockIdx.x * blockDim.x + threadIdx.x;
    if (e < EE) {
        atomicAdd(&g_outdeg[src[e]], 1);
        atomicAdd(&g_indeg[dst[e]], 1);
    }
}

// per-1024-chunk reduction of indeg -> g_partial[block]
__global__ void __launch_bounds__(256) scan_reduce_kernel() {
    __shared__ int s[256];
    int t = threadIdx.x;
    int base = blockIdx.x * 1024;
    int v = 0;
#pragma unroll
    for (int j = 0; j < 4; j++) {
        int i = base + t + j * 256;
        if (i < NN) v += g_indeg[i];
    }
    s[t] = v;
    __syncthreads();
    for (int off = 128; off > 0; off >>= 1) {
        if (t < off) s[t] += s[t + off];
        __syncthreads();
    }
    if (t == 0) g_partial[blockIdx.x] = s[0];
}

// single small block: exclusive scan of the partials
__global__ void __launch_bounds__(128) scan_partials_kernel(int nparts) {
    __shared__ int s[128];
    int t = threadIdx.x;
    int v = (t < nparts) ? g_partial[t] : 0;
    s[t] = v;
    __syncthreads();
    for (int off = 1; off < 128; off <<= 1) {
        int u = (t >= off) ? s[t - off] : 0;
        __syncthreads();
        s[t] += u;
        __syncthreads();
    }
    if (t < nparts) g_partial[t] = s[t] - v;  // exclusive
}

// downsweep: block-local exclusive scan + partial offset -> rowptr; also norms
__global__ void __launch_bounds__(1024) scan_down_kernel() {
    __shared__ int s[1024];
    int t = threadIdx.x;
    int i = blockIdx.x * 1024 + t;
    int d = (i < NN) ? g_indeg[i] : 0;
    s[t] = d;
    __syncthreads();
    for (int off = 1; off < 1024; off <<= 1) {
        int u = (t >= off) ? s[t - off] : 0;
        __syncthreads();
        s[t] += u;
        __syncthreads();
    }
    if (i < NN) {
        g_rowptr[i] = s[t] - d + g_partial[blockIdx.x];
        g_innorm[i]  = rsqrtf((float)max(d, 1));
        g_outnorm[i] = rsqrtf((float)max(g_outdeg[i], 1));
    }
    if (i == 0) g_rowptr[NN] = EE;
}

__global__ void __launch_bounds__(256) fill_kernel(const int* __restrict__ src, const int* __restrict__ dst) {
    int e = blockIdx.x * blockDim.x + threadIdx.x;
    if (e < EE) {
        int d = dst[e];
        int pos = atomicAdd(&g_cursor[d], 1);
        g_csrc[g_rowptr[d] + pos] = src[e];
    }
}

// ---------------- aggregation: one warp per node, register accumulation ----------------
// SCALE=true: multiply each gathered row by out_norm[src] on the fly (conv1 on raw x).
template <bool SCALE>
__global__ void __launch_bounds__(256) agg_kernel(const float4* __restrict__ X) {
    int w = (blockIdx.x * blockDim.x + threadIdx.x) >> 5;
    if (w >= NN) return;
    int lane = threadIdx.x & 31;
    int s = g_rowptr[w], e = g_rowptr[w + 1];
    float4 acc = make_float4(0.f, 0.f, 0.f, 0.f);
    int j = s;
    for (; j + 3 < e; j += 4) {
        int u0 = g_csrc[j], u1 = g_csrc[j + 1], u2 = g_csrc[j + 2], u3 = g_csrc[j + 3];
        float4 a = X[u0 * 32 + lane];
        float4 b = X[u1 * 32 + lane];
        float4 c = X[u2 * 32 + lane];
        float4 d = X[u3 * 32 + lane];
        if (SCALE) {
            float n0 = g_outnorm[u0], n1 = g_outnorm[u1], n2 = g_outnorm[u2], n3 = g_outnorm[u3];
            acc.x += a.x * n0 + b.x * n1 + c.x * n2 + d.x * n3;
            acc.y += a.y * n0 + b.y * n1 + c.y * n2 + d.y * n3;
            acc.z += a.z * n0 + b.z * n1 + c.z * n2 + d.z * n3;
            acc.w += a.w * n0 + b.w * n1 + c.w * n2 + d.w * n3;
        } else {
            acc.x += a.x + b.x + c.x + d.x;
            acc.y += a.y + b.y + c.y + d.y;
            acc.z += a.z + b.z + c.z + d.z;
            acc.w += a.w + b.w + c.w + d.w;
        }
    }
    for (; j < e; j++) {
        int u = g_csrc[j];
        float4 a = X[u * 32 + lane];
        float n = SCALE ? g_outnorm[u] : 1.f;
        acc.x += a.x * n; acc.y += a.y * n; acc.z += a.z * n; acc.w += a.w * n;
    }
    ((float4*)g_agg)[w * 32 + lane] = acc;
}

// ---------------- fused GEMM with packed f32x2 FMA ----------------
// out = act((prescale[r]*A) @ W + b) * postscale[r]
// A: [M,128] row-major, W: [128,BN] row-major. MODE: 0 = relu, 2 = sigmoid.
template <int BN, int MODE>
__global__ void __launch_bounds__(256) gemm_kernel(
    const float* __restrict__ A, const float* __restrict__ W,
    const float* __restrict__ bias,
    const float* __restrict__ prescale, const float* __restrict__ postscale,
    float* __restrict__ out, int M)
{
    constexpr int BM = 128, K = 128, BK = 32;
    constexpr int TM = 8;
    constexpr int TN = (BM * BN) / (256 * TM);  // 8 (BN=128) or 4 (BN=64)
    constexpr int TNP = TN / 2;
    __shared__ __align__(16) float As[BK][BM + 4];  // transposed A chunk
    __shared__ __align__(16) float Ws[BK][BN];

    int tid = threadIdx.x;
    int tx = tid & 15, ty = tid >> 4;
    int brow = blockIdx.x * BM;

    unsigned long long acc[TM][TNP];
#pragma unroll
    for (int i = 0; i < TM; i++)
#pragma unroll
        for (int j = 0; j < TNP; j++) acc[i][j] = 0ull;

    for (int k0 = 0; k0 < K; k0 += BK) {
        // load A chunk (BM x BK), transposed into smem
#pragma unroll
        for (int i = tid; i < BM * BK / 4; i += 256) {
            int r = i >> 3;    // / (BK/4)
            int kq = i & 7;
            int gr = brow + r;
            float4 v = (gr < M) ? *(const float4*)(A + (size_t)gr * K + k0 + kq * 4)
                                : make_float4(0.f, 0.f, 0.f, 0.f);
            As[kq * 4 + 0][r] = v.x;
            As[kq * 4 + 1][r] = v.y;
            As[kq * 4 + 2][r] = v.z;
            As[kq * 4 + 3][r] = v.w;
        }
        // load W chunk (BK x BN)
#pragma unroll
        for (int i = tid; i < BK * BN / 4; i += 256) {
            int kk = i / (BN / 4);
            int cq = i % (BN / 4);
            *(float4*)&Ws[kk][cq * 4] = *(const float4*)(W + (size_t)(k0 + kk) * BN + cq * 4);
        }
        __syncthreads();
#pragma unroll 8
        for (int k = 0; k < BK; k++) {
            float4 a0 = *(const float4*)&As[k][ty * TM];
            float4 a1 = *(const float4*)&As[k][ty * TM + 4];
            unsigned long long ap[TM];
            ap[0] = pack2_dup(a0.x); ap[1] = pack2_dup(a0.y);
            ap[2] = pack2_dup(a0.z); ap[3] = pack2_dup(a0.w);
            ap[4] = pack2_dup(a1.x); ap[5] = pack2_dup(a1.y);
            ap[6] = pack2_dup(a1.z); ap[7] = pack2_dup(a1.w);
            unsigned long long bp[TNP];
            if (TN == 8) {
                ulonglong2 q0 = *(const ulonglong2*)&Ws[k][tx * TN];
                ulonglong2 q1 = *(const ulonglong2*)&Ws[k][tx * TN + 4];
                bp[0] = q0.x; bp[1] = q0.y;
                bp[2] = q1.x; bp[3] = q1.y;
            } else {
                ulonglong2 q0 = *(const ulonglong2*)&Ws[k][tx * TN];
                bp[0] = q0.x; bp[1] = q0.y;
            }
#pragma unroll
            for (int i = 0; i < TM; i++)
#pragma unroll
                for (int j = 0; j < TNP; j++)
                    fma2(acc[i][j], ap[i], bp[j]);
        }
        __syncthreads();
    }

    // epilogue
#pragma unroll
    for (int i = 0; i < TM; i++) {
        int r = brow + ty * TM + i;
        if (r < M) {
            float ps = prescale ? prescale[r] : 1.f;
            float posts = postscale ? postscale[r] : 1.f;
            float o[TN];
#pragma unroll
            for (int j = 0; j < TNP; j++) {
                float2 v = unpack2(acc[i][j]);
                o[2 * j] = v.x;
                o[2 * j + 1] = v.y;
            }
#pragma unroll
            for (int c = 0; c < TN; c++) {
                float v = o[c] * ps + bias[tx * TN + c];
                if (MODE == 2) {
                    v = 1.f / (1.f + __expf(-v));
                } else {
                    v = fmaxf(v, 0.f) * posts;
                }
                o[c] = v;
            }
#pragma unroll
            for (int c = 0; c < TN; c += 4) {
                float4 v4 = make_float4(o[c], o[c + 1], o[c + 2], o[c + 3]);
                *(float4*)(out + (size_t)r * BN + tx * TN + c) = v4;
            }
        }
    }
}

// ---------------- launch ----------------
extern "C" void kernel_launch(void* const* d_in, const int* in_sizes, int n_in,
                              void* d_out, int out_size) {
    const float* x   = (const float*)d_in[0];
    const int*   src = (const int*)d_in[1];
    const int*   dst = (const int*)d_in[2];
    const float* W1  = (const float*)d_in[3];
    const float* b1  = (const float*)d_in[4];
    const float* W2  = (const float*)d_in[5];
    const float* b2  = (const float*)d_in[6];
    const float* Wm1 = (const float*)d_in[7];
    const float* bm1 = (const float*)d_in[8];
    const float* Wm2 = (const float*)d_in[9];
    const float* bm2 = (const float*)d_in[10];
    float* out = (float*)d_out;

    void *p_xs, *p_agg, *p_h, *p_innorm, *p_outnorm;
    cudaGetSymbolAddress(&p_xs, g_xs);
    cudaGetSymbolAddress(&p_agg, g_agg);
    cudaGetSymbolAddress(&p_h, g_h);
    cudaGetSymbolAddress(&p_innorm, g_innorm);
    cudaGetSymbolAddress(&p_outnorm, g_outnorm);

    const int TB = 256;
    int nblk = (NN + TB - 1) / TB;
    int eblk = (EE + TB - 1) / TB;
    int sblk = (NN + 1023) / 1024;  // 98

    // graph preprocessing: degrees, norms, CSR-by-dst
    zero_kernel<<<nblk, TB>>>();
    degree_kernel<<<eblk, TB>>>(src, dst);
    scan_reduce_kernel<<<sblk, 256>>>();
    scan_partials_kernel<<<1, 128>>>(sblk);
    scan_down_kernel<<<sblk, 1024>>>();
    fill_kernel<<<eblk, TB>>>(src, dst);

    int ablk = (NN * 32 + TB - 1) / TB;

    // conv1: gather raw x scaled by out_norm[src] on the fly
    agg_kernel<true><<<ablk, TB>>>((const float4*)x);
    // h1 = relu((agg * in_norm) @ W1 + b1); stage h1*out_norm into g_xs for conv2 gather
    gemm_kernel<128, 0><<<(NN + 127) / 128, 256>>>(
        (const float*)p_agg, W1, b1, (const float*)p_innorm, (const float*)p_outnorm,
        (float*)p_xs, NN);

    // conv2
    agg_kernel<false><<<ablk, TB>>>((const float4*)p_xs);
    gemm_kernel<128, 0><<<(NN + 127) / 128, 256>>>(
        (const float*)p_agg, W2, b2, (const float*)p_innorm, nullptr,
        (float*)p_h, NN);

    // MLP head
    gemm_kernel<128, 0><<<(NN + 127) / 128, 256>>>(
        (const float*)p_h, Wm1, bm1, nullptr, nullptr, (float*)p_xs, NN);
    gemm_kernel<64, 2><<<(NN + 127) / 128, 256>>>(
        (const float*)p_xs, Wm2, bm2, nullptr, nullptr, out, NN);
}

// round 5
// speedup vs baseline: 1.4019x; 1.0521x over previous
#include <cuda_runtime.h>
#include <cuda_bf16.h>
#include <math.h>

#define NN 100000
#define EE 3200000
#define FF 128

// ---------------- static device scratch (no allocations allowed) ----------------
__device__ __nv_bfloat16 g_xb[NN * FF];  // bf16 gather source (x, then h1*outnorm)
__device__ float g_agg[NN * FF];         // aggregation result / MLP intermediate
__device__ float g_h[NN * FF];           // hidden activations (conv2 output)
__device__ float g_outnorm[NN];
__device__ float g_innorm[NN];
__device__ int   g_outdeg[NN];
__device__ int   g_indeg[NN];
__device__ int   g_rowptr[NN + 1];
__device__ int   g_cursor[NN];
__device__ int   g_partial[128];
__device__ int   g_csrc[EE];             // CSR (by dst) column indices = src nodes

// ---------------- f32x2 packed helpers ----------------
__device__ __forceinline__ unsigned long long pack2_dup(float x) {
    unsigned long long r;
    asm("mov.b64 %0, {%1, %1};" : "=l"(r) : "r"(__float_as_uint(x)));
    return r;
}
__device__ __forceinline__ void fma2(unsigned long long& d, unsigned long long a, unsigned long long b) {
    asm("fma.rn.f32x2 %0, %1, %2, %0;" : "+l"(d) : "l"(a), "l"(b));
}
__device__ __forceinline__ float2 unpack2(unsigned long long v) {
    unsigned int lo, hi;
    asm("mov.b64 {%0, %1}, %2;" : "=r"(lo), "=r"(hi) : "l"(v));
    float2 r; r.x = __uint_as_float(lo); r.y = __uint_as_float(hi);
    return r;
}

// 8 bf16 (uint2) -> float4 (4 lanes worth handled per lane: 4 feats)
__device__ __forceinline__ float4 bf4_to_f4(uint2 p) {
    __nv_bfloat162 b0 = *reinterpret_cast<__nv_bfloat162*>(&p.x);
    __nv_bfloat162 b1 = *reinterpret_cast<__nv_bfloat162*>(&p.y);
    float2 f0 = __bfloat1622float2(b0);
    float2 f1 = __bfloat1622float2(b1);
    return make_float4(f0.x, f0.y, f1.x, f1.y);
}

// ---------------- graph preprocessing ----------------
__global__ void __launch_bounds__(256) zero_kernel() {
    int i = blockIdx.x * blockDim.x + threadIdx.x;
    if (i < NN) { g_outdeg[i] = 0; g_indeg[i] = 0; }
}

__global__ void __launch_bounds__(256) degree_kernel(const int* __restrict__ src, const int* __restrict__ dst) {
    int e = blockIdx.x * blockDim.x + threadIdx.x;
    if (e < EE) {
        atomicAdd(&g_outdeg[src[e]], 1);
        atomicAdd(&g_indeg[dst[e]], 1);
    }
}

// per-1024-chunk reduction of indeg -> g_partial[block]
__global__ void __launch_bounds__(256) scan_reduce_kernel() {
    __shared__ int s[256];
    int t = threadIdx.x;
    int base = blockIdx.x * 1024;
    int v = 0;
#pragma unroll
    for (int j = 0; j < 4; j++) {
        int i = base + t + j * 256;
        if (i < NN) v += g_indeg[i];
    }
    s[t] = v;
    __syncthreads();
    for (int off = 128; off > 0; off >>= 1) {
        if (t < off) s[t] += s[t + off];
        __syncthreads();
    }
    if (t == 0) g_partial[blockIdx.x] = s[0];
}

// single small block: exclusive scan of the partials
__global__ void __launch_bounds__(128) scan_partials_kernel(int nparts) {
    __shared__ int s[128];
    int t = threadIdx.x;
    int v = (t < nparts) ? g_partial[t] : 0;
    s[t] = v;
    __syncthreads();
    for (int off = 1; off < 128; off <<= 1) {
        int u = (t >= off) ? s[t - off] : 0;
        __syncthreads();
        s[t] += u;
        __syncthreads();
    }
    if (t < nparts) g_partial[t] = s[t] - v;  // exclusive
}

// downsweep: rowptr (+ cursor copy for fill) + norms
__global__ void __launch_bounds__(1024) scan_down_kernel() {
    __shared__ int s[1024];
    int t = threadIdx.x;
    int i = blockIdx.x * 1024 + t;
    int d = (i < NN) ? g_indeg[i] : 0;
    s[t] = d;
    __syncthreads();
    for (int off = 1; off < 1024; off <<= 1) {
        int u = (t >= off) ? s[t - off] : 0;
        __syncthreads();
        s[t] += u;
        __syncthreads();
    }
    if (i < NN) {
        int rp = s[t] - d + g_partial[blockIdx.x];
        g_rowptr[i] = rp;
        g_cursor[i] = rp;  // fill kernel bumps this directly
        g_innorm[i]  = rsqrtf((float)max(d, 1));
        g_outnorm[i] = rsqrtf((float)max(g_outdeg[i], 1));
    }
    if (i == 0) g_rowptr[NN] = EE;
}

__global__ void __launch_bounds__(256) fill_kernel(const int* __restrict__ src, const int* __restrict__ dst) {
    int e = blockIdx.x * blockDim.x + threadIdx.x;
    if (e < EE) {
        int pos = atomicAdd(&g_cursor[dst[e]], 1);
        g_csrc[pos] = src[e];
    }
}

// ---------------- x -> bf16 conversion ----------------
__global__ void __launch_bounds__(256) tobf16_kernel(const float4* __restrict__ x) {
    int i = blockIdx.x * blockDim.x + threadIdx.x;  // over NN*32 float4s
    if (i < NN * 32) {
        float4 v = x[i];
        __nv_bfloat162 b0 = __floats2bfloat162_rn(v.x, v.y);
        __nv_bfloat162 b1 = __floats2bfloat162_rn(v.z, v.w);
        uint2 p;
        p.x = *reinterpret_cast<unsigned*>(&b0);
        p.y = *reinterpret_cast<unsigned*>(&b1);
        ((uint2*)g_xb)[i] = p;
    }
}

// ---------------- aggregation: one warp per node, bf16 gather, fp32 accumulate ----------------
// SCALE=true: multiply each gathered row by out_norm[src] on the fly (conv1).
template <bool SCALE>
__global__ void __launch_bounds__(256) agg_kernel() {
    int w = (blockIdx.x * blockDim.x + threadIdx.x) >> 5;
    if (w >= NN) return;
    int lane = threadIdx.x & 31;
    int s = g_rowptr[w], e = g_rowptr[w + 1];
    const uint2* __restrict__ X = (const uint2*)g_xb;  // 4 bf16 pairs... 8B = 4 feats/lane
    float4 acc = make_float4(0.f, 0.f, 0.f, 0.f);
    int j = s;
    for (; j + 3 < e; j += 4) {
        int u0 = g_csrc[j], u1 = g_csrc[j + 1], u2 = g_csrc[j + 2], u3 = g_csrc[j + 3];
        float4 a = bf4_to_f4(X[u0 * 32 + lane]);
        float4 b = bf4_to_f4(X[u1 * 32 + lane]);
        float4 c = bf4_to_f4(X[u2 * 32 + lane]);
        float4 d = bf4_to_f4(X[u3 * 32 + lane]);
        if (SCALE) {
            float n0 = g_outnorm[u0], n1 = g_outnorm[u1], n2 = g_outnorm[u2], n3 = g_outnorm[u3];
            acc.x += a.x * n0 + b.x * n1 + c.x * n2 + d.x * n3;
            acc.y += a.y * n0 + b.y * n1 + c.y * n2 + d.y * n3;
            acc.z += a.z * n0 + b.z * n1 + c.z * n2 + d.z * n3;
            acc.w += a.w * n0 + b.w * n1 + c.w * n2 + d.w * n3;
        } else {
            acc.x += a.x + b.x + c.x + d.x;
            acc.y += a.y + b.y + c.y + d.y;
            acc.z += a.z + b.z + c.z + d.z;
            acc.w += a.w + b.w + c.w + d.w;
        }
    }
    for (; j < e; j++) {
        int u = g_csrc[j];
        float4 a = bf4_to_f4(X[u * 32 + lane]);
        float n = SCALE ? g_outnorm[u] : 1.f;
        acc.x += a.x * n; acc.y += a.y * n; acc.z += a.z * n; acc.w += a.w * n;
    }
    // lane covers feats [lane*4, lane*4+4)
    ((float4*)g_agg)[w * 32 + lane] = acc;
}

// ---------------- fused GEMM with packed f32x2 FMA ----------------
// out = act((prescale[r]*A) @ W + b) * postscale[r]
// A: [M,128] row-major, W: [128,BN] row-major. MODE: 0 = relu, 2 = sigmoid.
// OUTB: write output as bf16 (requires BN=128).
template <int BN, int MODE, bool OUTB>
__global__ void __launch_bounds__(256) gemm_kernel(
    const float* __restrict__ A, const float* __restrict__ W,
    const float* __restrict__ bias,
    const float* __restrict__ prescale, const float* __restrict__ postscale,
    float* __restrict__ out, int M)
{
    constexpr int BM = 128, K = 128, BK = 32;
    constexpr int TM = 8;
    constexpr int TN = (BM * BN) / (256 * TM);  // 8 (BN=128) or 4 (BN=64)
    constexpr int TNP = TN / 2;
    __shared__ __align__(16) float As[BK][BM + 4];  // transposed A chunk
    __shared__ __align__(16) float Ws[BK][BN];

    int tid = threadIdx.x;
    int tx = tid & 15, ty = tid >> 4;
    int brow = blockIdx.x * BM;

    unsigned long long acc[TM][TNP];
#pragma unroll
    for (int i = 0; i < TM; i++)
#pragma unroll
        for (int j = 0; j < TNP; j++) acc[i][j] = 0ull;

    for (int k0 = 0; k0 < K; k0 += BK) {
        // load A chunk (BM x BK), transposed into smem
#pragma unroll
        for (int i = tid; i < BM * BK / 4; i += 256) {
            int r = i >> 3;    // / (BK/4)
            int kq = i & 7;
            int gr = brow + r;
            float4 v = (gr < M) ? *(const float4*)(A + (size_t)gr * K + k0 + kq * 4)
                                : make_float4(0.f, 0.f, 0.f, 0.f);
            As[kq * 4 + 0][r] = v.x;
            As[kq * 4 + 1][r] = v.y;
            As[kq * 4 + 2][r] = v.z;
            As[kq * 4 + 3][r] = v.w;
        }
        // load W chunk (BK x BN)
#pragma unroll
        for (int i = tid; i < BK * BN / 4; i += 256) {
            int kk = i / (BN / 4);
            int cq = i % (BN / 4);
            *(float4*)&Ws[kk][cq * 4] = *(const float4*)(W + (size_t)(k0 + kk) * BN + cq * 4);
        }
        __syncthreads();
#pragma unroll 8
        for (int k = 0; k < BK; k++) {
            float4 a0 = *(const float4*)&As[k][ty * TM];
            float4 a1 = *(const float4*)&As[k][ty * TM + 4];
            unsigned long long ap[TM];
            ap[0] = pack2_dup(a0.x); ap[1] = pack2_dup(a0.y);
            ap[2] = pack2_dup(a0.z); ap[3] = pack2_dup(a0.w);
            ap[4] = pack2_dup(a1.x); ap[5] = pack2_dup(a1.y);
            ap[6] = pack2_dup(a1.z); ap[7] = pack2_dup(a1.w);
            unsigned long long bp[TNP];
            if (TN == 8) {
                ulonglong2 q0 = *(const ulonglong2*)&Ws[k][tx * TN];
                ulonglong2 q1 = *(const ulonglong2*)&Ws[k][tx * TN + 4];
                bp[0] = q0.x; bp[1] = q0.y;
                bp[2] = q1.x; bp[3] = q1.y;
            } else {
                ulonglong2 q0 = *(const ulonglong2*)&Ws[k][tx * TN];
                bp[0] = q0.x; bp[1] = q0.y;
            }
#pragma unroll
            for (int i = 0; i < TM; i++)
#pragma unroll
                for (int j = 0; j < TNP; j++)
                    fma2(acc[i][j], ap[i], bp[j]);
        }
        __syncthreads();
    }

    // epilogue
#pragma unroll
    for (int i = 0; i < TM; i++) {
        int r = brow + ty * TM + i;
        if (r < M) {
            float ps = prescale ? prescale[r] : 1.f;
            float posts = postscale ? postscale[r] : 1.f;
            float o[TN];
#pragma unroll
            for (int j = 0; j < TNP; j++) {
                float2 v = unpack2(acc[i][j]);
                o[2 * j] = v.x;
                o[2 * j + 1] = v.y;
            }
#pragma unroll
            for (int c = 0; c < TN; c++) {
                float v = o[c] * ps + bias[tx * TN + c];
                if (MODE == 2) {
                    v = 1.f / (1.f + __expf(-v));
                } else {
                    v = fmaxf(v, 0.f) * posts;
                }
                o[c] = v;
            }
            if (OUTB) {
                // pack TN=8 outputs into 8 bf16 = 16 bytes
                __nv_bfloat162 h0 = __floats2bfloat162_rn(o[0], o[1]);
                __nv_bfloat162 h1 = __floats2bfloat162_rn(o[2], o[3]);
                __nv_bfloat162 h2 = __floats2bfloat162_rn(o[4], o[5]);
                __nv_bfloat162 h3 = __floats2bfloat162_rn(o[6], o[7]);
                uint4 pk;
                pk.x = *reinterpret_cast<unsigned*>(&h0);
                pk.y = *reinterpret_cast<unsigned*>(&h1);
                pk.z = *reinterpret_cast<unsigned*>(&h2);
                pk.w = *reinterpret_cast<unsigned*>(&h3);
                *(uint4*)((__nv_bfloat16*)out + (size_t)r * BN + tx * TN) = pk;
            } else {
#pragma unroll
                for (int c = 0; c < TN; c += 4) {
                    float4 v4 = make_float4(o[c], o[c + 1], o[c + 2], o[c + 3]);
                    *(float4*)(out + (size_t)r * BN + tx * TN + c) = v4;
                }
            }
        }
    }
}

// ---------------- launch ----------------
extern "C" void kernel_launch(void* const* d_in, const int* in_sizes, int n_in,
                              void* d_out, int out_size) {
    const float* x   = (const float*)d_in[0];
    const int*   src = (const int*)d_in[1];
    const int*   dst = (const int*)d_in[2];
    const float* W1  = (const float*)d_in[3];
    const float* b1  = (const float*)d_in[4];
    const float* W2  = (const float*)d_in[5];
    const float* b2  = (const float*)d_in[6];
    const float* Wm1 = (const float*)d_in[7];
    const float* bm1 = (const float*)d_in[8];
    const float* Wm2 = (const float*)d_in[9];
    const float* bm2 = (const float*)d_in[10];
    float* out = (float*)d_out;

    void *p_xb, *p_agg, *p_h, *p_innorm, *p_outnorm;
    cudaGetSymbolAddress(&p_xb, g_xb);
    cudaGetSymbolAddress(&p_agg, g_agg);
    cudaGetSymbolAddress(&p_h, g_h);
    cudaGetSymbolAddress(&p_innorm, g_innorm);
    cudaGetSymbolAddress(&p_outnorm, g_outnorm);

    const int TB = 256;
    int nblk = (NN + TB - 1) / TB;
    int eblk = (EE + TB - 1) / TB;
    int sblk = (NN + 1023) / 1024;  // 98

    // graph preprocessing: degrees, norms, CSR-by-dst
    zero_kernel<<<nblk, TB>>>();
    degree_kernel<<<eblk, TB>>>(src, dst);
    scan_reduce_kernel<<<sblk, 256>>>();
    scan_partials_kernel<<<1, 128>>>(sblk);
    scan_down_kernel<<<sblk, 1024>>>();
    fill_kernel<<<eblk, TB>>>(src, dst);

    int ablk = (NN * 32 + TB - 1) / TB;

    // x -> bf16 gather source
    tobf16_kernel<<<(NN * 32 + TB - 1) / TB, TB>>>((const float4*)x);

    // conv1: gather bf16 x scaled by out_norm[src] on the fly
    agg_kernel<true><<<ablk, TB>>>();
    // h1 = relu((agg * in_norm) @ W1 + b1); stage h1*out_norm as bf16 into g_xb
    gemm_kernel<128, 0, true><<<(NN + 127) / 128, 256>>>(
        (const float*)p_agg, W1, b1, (const float*)p_innorm, (const float*)p_outnorm,
        (float*)p_xb, NN);

    // conv2
    agg_kernel<false><<<ablk, TB>>>();
    gemm_kernel<128, 0, false><<<(NN + 127) / 128, 256>>>(
        (const float*)p_agg, W2, b2, (const float*)p_innorm, nullptr,
        (float*)p_h, NN);

    // MLP head (reuse g_agg for the intermediate)
    gemm_kernel<128, 0, false><<<(NN + 127) / 128, 256>>>(
        (const float*)p_h, Wm1, bm1, nullptr, nullptr, (float*)p_agg, NN);
    gemm_kernel<64, 2, false><<<(NN + 127) / 128, 256>>>(
        (const float*)p_agg, Wm2, bm2, nullptr, nullptr, out, NN);
}

// round 10
// speedup vs baseline: 2.2848x; 1.6298x over previous
#include <cuda_runtime.h>
#include <cuda_bf16.h>
#include <cstdint>
#include <math.h>

#define NN 100000
#define EE 3200000
#define FF 128

// ---------------- static device scratch (no allocations allowed) ----------------
__device__ __nv_bfloat16 g_xb[NN * FF];   // bf16 gather source (x, then h1*outnorm)
__device__ __nv_bfloat16 g_aggb[NN * FF]; // bf16 aggregation output (x innorm)
__device__ __nv_bfloat16 g_hb[NN * FF];   // conv2 output
__device__ __nv_bfloat16 g_mb[NN * FF];   // mlp hidden
__device__ __nv_bfloat16 g_w1t[FF * FF];  // W1^T bf16 [n][k]
__device__ __nv_bfloat16 g_w2t[FF * FF];
__device__ __nv_bfloat16 g_wm1t[FF * FF];
__device__ __nv_bfloat16 g_wm2t[64 * FF];
__device__ float g_outnorm[NN];
__device__ float g_innorm[NN];
__device__ int   g_outdeg[NN];
__device__ int   g_indeg[NN];
__device__ int   g_rowptr[NN + 1];
__device__ int   g_cursor[NN];
__device__ int   g_partial[128];
__device__ int   g_csrc[EE];              // CSR (by dst) column indices = src nodes

// ---------------- graph preprocessing ----------------
__global__ void __launch_bounds__(256) zero_kernel() {
    int i = blockIdx.x * blockDim.x + threadIdx.x;
    if (i < NN) { g_outdeg[i] = 0; g_indeg[i] = 0; }
}

__global__ void __launch_bounds__(256) degree_kernel(const int* __restrict__ src, const int* __restrict__ dst) {
    int e = blockIdx.x * blockDim.x + threadIdx.x;
    if (e < EE) {
        atomicAdd(&g_outdeg[src[e]], 1);
        atomicAdd(&g_indeg[dst[e]], 1);
    }
}

__global__ void __launch_bounds__(256) scan_reduce_kernel() {
    __shared__ int s[256];
    int t = threadIdx.x;
    int base = blockIdx.x * 1024;
    int v = 0;
#pragma unroll
    for (int j = 0; j < 4; j++) {
        int i = base + t + j * 256;
        if (i < NN) v += g_indeg[i];
    }
    s[t] = v;
    __syncthreads();
    for (int off = 128; off > 0; off >>= 1) {
        if (t < off) s[t] += s[t + off];
        __syncthreads();
    }
    if (t == 0) g_partial[blockIdx.x] = s[0];
}

__global__ void __launch_bounds__(128) scan_partials_kernel(int nparts) {
    __shared__ int s[128];
    int t = threadIdx.x;
    int v = (t < nparts) ? g_partial[t] : 0;
    s[t] = v;
    __syncthreads();
    for (int off = 1; off < 128; off <<= 1) {
        int u = (t >= off) ? s[t - off] : 0;
        __syncthreads();
        s[t] += u;
        __syncthreads();
    }
    if (t < nparts) g_partial[t] = s[t] - v;
}

__global__ void __launch_bounds__(1024) scan_down_kernel() {
    __shared__ int s[1024];
    int t = threadIdx.x;
    int i = blockIdx.x * 1024 + t;
    int d = (i < NN) ? g_indeg[i] : 0;
    s[t] = d;
    __syncthreads();
    for (int off = 1; off < 1024; off <<= 1) {
        int u = (t >= off) ? s[t - off] : 0;
        __syncthreads();
        s[t] += u;
        __syncthreads();
    }
    if (i < NN) {
        int rp = s[t] - d + g_partial[blockIdx.x];
        g_rowptr[i] = rp;
        g_cursor[i] = rp;
        g_innorm[i]  = rsqrtf((float)max(d, 1));
        g_outnorm[i] = rsqrtf((float)max(g_outdeg[i], 1));
    }
    if (i == 0) g_rowptr[NN] = EE;
}

__global__ void __launch_bounds__(256) fill_kernel(const int* __restrict__ src, const int* __restrict__ dst) {
    int e = blockIdx.x * blockDim.x + threadIdx.x;
    if (e < EE) {
        int pos = atomicAdd(&g_cursor[dst[e]], 1);
        g_csrc[pos] = src[e];
    }
}

// ---------------- x -> bf16 ----------------
__global__ void __launch_bounds__(256) tobf16_kernel(const float4* __restrict__ x) {
    int i = blockIdx.x * blockDim.x + threadIdx.x;
    if (i < NN * 32) {
        float4 v = x[i];
        __nv_bfloat162 b0 = __floats2bfloat162_rn(v.x, v.y);
        __nv_bfloat162 b1 = __floats2bfloat162_rn(v.z, v.w);
        uint2 p;
        p.x = *reinterpret_cast<unsigned*>(&b0);
        p.y = *reinterpret_cast<unsigned*>(&b1);
        ((uint2*)g_xb)[i] = p;
    }
}

// ---------------- weight prep: transpose + bf16 ----------------
__global__ void __launch_bounds__(256) wt_kernel(
    const float* __restrict__ W1, const float* __restrict__ W2,
    const float* __restrict__ Wm1, const float* __restrict__ Wm2) {
    int i = blockIdx.x * blockDim.x + threadIdx.x;
    if (i < 16384) {
        int k = i >> 7, n = i & 127;
        g_w1t[n * 128 + k] = __float2bfloat16(W1[i]);
    } else if (i < 32768) {
        int j = i - 16384; int k = j >> 7, n = j & 127;
        g_w2t[n * 128 + k] = __float2bfloat16(W2[j]);
    } else if (i < 49152) {
        int j = i - 32768; int k = j >> 7, n = j & 127;
        g_wm1t[n * 128 + k] = __float2bfloat16(Wm1[j]);
    } else if (i < 57344) {
        int j = i - 49152; int k = j >> 6, n = j & 63;
        g_wm2t[n * 128 + k] = __float2bfloat16(Wm2[j]);
    }
}

// ---------------- aggregation: one warp per node, bf16 gather, fp32 accum, bf16 out ----------------
__device__ __forceinline__ float4 bf4_to_f4(uint2 p) {
    __nv_bfloat162 b0 = *reinterpret_cast<__nv_bfloat162*>(&p.x);
    __nv_bfloat162 b1 = *reinterpret_cast<__nv_bfloat162*>(&p.y);
    float2 f0 = __bfloat1622float2(b0);
    float2 f1 = __bfloat1622float2(b1);
    return make_float4(f0.x, f0.y, f1.x, f1.y);
}

template <bool SCALE>
__global__ void __launch_bounds__(256) agg_kernel() {
    int w = (blockIdx.x * blockDim.x + threadIdx.x) >> 5;
    if (w >= NN) return;
    int lane = threadIdx.x & 31;
    int s = g_rowptr[w], e = g_rowptr[w + 1];
    const uint2* __restrict__ X = (const uint2*)g_xb;
    float4 acc = make_float4(0.f, 0.f, 0.f, 0.f);
    int j = s;
    for (; j + 3 < e; j += 4) {
        int u0 = g_csrc[j], u1 = g_csrc[j + 1], u2 = g_csrc[j + 2], u3 = g_csrc[j + 3];
        float4 a = bf4_to_f4(X[u0 * 32 + lane]);
        float4 b = bf4_to_f4(X[u1 * 32 + lane]);
        float4 c = bf4_to_f4(X[u2 * 32 + lane]);
        float4 d = bf4_to_f4(X[u3 * 32 + lane]);
        if (SCALE) {
            float n0 = g_outnorm[u0], n1 = g_outnorm[u1], n2 = g_outnorm[u2], n3 = g_outnorm[u3];
            acc.x += a.x * n0 + b.x * n1 + c.x * n2 + d.x * n3;
            acc.y += a.y * n0 + b.y * n1 + c.y * n2 + d.y * n3;
            acc.z += a.z * n0 + b.z * n1 + c.z * n2 + d.z * n3;
            acc.w += a.w * n0 + b.w * n1 + c.w * n2 + d.w * n3;
        } else {
            acc.x += a.x + b.x + c.x + d.x;
            acc.y += a.y + b.y + c.y + d.y;
            acc.z += a.z + b.z + c.z + d.z;
            acc.w += a.w + b.w + c.w + d.w;
        }
    }
    for (; j < e; j++) {
        int u = g_csrc[j];
        float4 a = bf4_to_f4(X[u * 32 + lane]);
        float n = SCALE ? g_outnorm[u] : 1.f;
        acc.x += a.x * n; acc.y += a.y * n; acc.z += a.z * n; acc.w += a.w * n;
    }
    float inw = g_innorm[w];
    acc.x *= inw; acc.y *= inw; acc.z *= inw; acc.w *= inw;
    __nv_bfloat162 b0 = __floats2bfloat162_rn(acc.x, acc.y);
    __nv_bfloat162 b1 = __floats2bfloat162_rn(acc.z, acc.w);
    uint2 p;
    p.x = *reinterpret_cast<unsigned*>(&b0);
    p.y = *reinterpret_cast<unsigned*>(&b1);
    ((uint2*)g_aggb)[w * 32 + lane] = p;
}

// ---------------- mma.sync bf16 GEMM: D[M,NR] = A[M,128] @ Bt[NR,128]^T ----------------
// A row-major [M,128] bf16, Bt row-major [NR,128] bf16 (= B col-major).
// epilogue: v = D + bias[c]; MODE 0: relu (*postscale[r] if POST); MODE 2: sigmoid.
// OUTB: bf16 output; else fp32. 256 threads: warp grid 4 (M) x 2 (N).
template <int NR, int MODE, bool OUTB, bool POST>
__global__ void __launch_bounds__(256) mma_gemm_kernel(
    const __nv_bfloat16* __restrict__ A,
    const __nv_bfloat16* __restrict__ Bt,
    const float* __restrict__ bias,
    const float* __restrict__ postscale,
    void* __restrict__ outp, int M)
{
    constexpr int K = 128;
    constexpr int SA = 136;                // row stride in bf16 elems (+16B pad -> conflict-free frags)
    constexpr int NT = NR / 16;            // n-tiles (8 wide) per warp: 8 (NR=128) or 4 (NR=64)
    extern __shared__ char smem[];
    __nv_bfloat16* As = (__nv_bfloat16*)smem;                       // 128 x SA
    __nv_bfloat16* Bs = (__nv_bfloat16*)(smem + 128 * SA * 2);      // NR x SA
    float* bs = (float*)(smem + 128 * SA * 2 + NR * SA * 2);

    int tid = threadIdx.x;
    int brow = blockIdx.x * 128;

    // load A tile (uint4 per 8 elems)
    for (int i = tid; i < 128 * 16; i += 256) {
        int row = i >> 4, seg = i & 15;
        uint4 v = make_uint4(0u, 0u, 0u, 0u);
        int gr = brow + row;
        if (gr < M) v = *(const uint4*)(A + (size_t)gr * K + seg * 8);
        *(uint4*)(As + row * SA + seg * 8) = v;
    }
    // load B tile
    for (int i = tid; i < NR * 16; i += 256) {
        int row = i >> 4, seg = i & 15;
        *(uint4*)(Bs + row * SA + seg * 8) = *(const uint4*)(Bt + (size_t)row * K + seg * 8);
    }
    if (tid < NR) bs[tid] = bias[tid];
    __syncthreads();

    int wid = tid >> 5, lane = tid & 31;
    int wm = wid & 3, wn = wid >> 2;       // wm: 0..3 (32 rows each), wn: 0..1 (NR/2 cols each)
    int gid = lane >> 2, tig = lane & 3;

    float c[2][NT][4];
#pragma unroll
    for (int mt = 0; mt < 2; mt++)
#pragma unroll
        for (int nt = 0; nt < NT; nt++)
#pragma unroll
            for (int q = 0; q < 4; q++) c[mt][nt][q] = 0.f;

#pragma unroll
    for (int ks = 0; ks < 8; ks++) {
        int k0 = ks * 16;
        unsigned af[2][4];
#pragma unroll
        for (int mt = 0; mt < 2; mt++) {
            const __nv_bfloat16* p = As + (wm * 32 + mt * 16 + gid) * SA + k0 + tig * 2;
            af[mt][0] = *(const unsigned*)(p);
            af[mt][1] = *(const unsigned*)(p + 8 * SA);
            af[mt][2] = *(const unsigned*)(p + 8);
            af[mt][3] = *(const unsigned*)(p + 8 * SA + 8);
        }
        unsigned bf[NT][2];
#pragma unroll
        for (int nt = 0; nt < NT; nt++) {
            const __nv_bfloat16* q = Bs + (wn * (NT * 8) + nt * 8 + gid) * SA + k0 + tig * 2;
            bf[nt][0] = *(const unsigned*)(q);
            bf[nt][1] = *(const unsigned*)(q + 8);
        }
#pragma unroll
        for (int mt = 0; mt < 2; mt++)
#pragma unroll
            for (int nt = 0; nt < NT; nt++) {
                asm volatile(
                    "mma.sync.aligned.m16n8k16.row.col.f32.bf16.bf16.f32 "
                    "{%0,%1,%2,%3}, {%4,%5,%6,%7}, {%8,%9}, {%0,%1,%2,%3};"
                    : "+f"(c[mt][nt][0]), "+f"(c[mt][nt][1]),
                      "+f"(c[mt][nt][2]), "+f"(c[mt][nt][3])
                    : "r"(af[mt][0]), "r"(af[mt][1]), "r"(af[mt][2]), "r"(af[mt][3]),
                      "r"(bf[nt][0]), "r"(bf[nt][1]));
            }
    }

    // epilogue: c0,c1 -> (r, col..col+1); c2,c3 -> (r+8, col..col+1)
#pragma unroll
    for (int mt = 0; mt < 2; mt++) {
        int r0 = brow + wm * 32 + mt * 16 + gid;
        int r1 = r0 + 8;
        float p0 = 1.f, p1 = 1.f;
        if (POST) {
            if (r0 < M) p0 = postscale[r0];
            if (r1 < M) p1 = postscale[r1];
        }
#pragma unroll
        for (int nt = 0; nt < NT; nt++) {
            int col = wn * (NT * 8) + nt * 8 + tig * 2;
            float b0v = bs[col], b1v = bs[col + 1];
            float v0 = c[mt][nt][0] + b0v, v1 = c[mt][nt][1] + b1v;
            float v2 = c[mt][nt][2] + b0v, v3 = c[mt][nt][3] + b1v;
            if (MODE == 2) {
                v0 = 1.f / (1.f + __expf(-v0)); v1 = 1.f / (1.f + __expf(-v1));
                v2 = 1.f / (1.f + __expf(-v2)); v3 = 1.f / (1.f + __expf(-v3));
            } else {
                v0 = fmaxf(v0, 0.f) * p0; v1 = fmaxf(v1, 0.f) * p0;
                v2 = fmaxf(v2, 0.f) * p1; v3 = fmaxf(v3, 0.f) * p1;
            }
            if (OUTB) {
                __nv_bfloat16* ob = (__nv_bfloat16*)outp;
                if (r0 < M) {
                    __nv_bfloat162 pk = __floats2bfloat162_rn(v0, v1);
                    *(unsigned*)(ob + (size_t)r0 * NR + col) = *reinterpret_cast<unsigned*>(&pk);
                }
                if (r1 < M) {
                    __nv_bfloat162 pk = __floats2bfloat162_rn(v2, v3);
                    *(unsigned*)(ob + (size_t)r1 * NR + col) = *reinterpret_cast<unsigned*>(&pk);
                }
            } else {
                float* of = (float*)outp;
                if (r0 < M) *(float2*)(of + (size_t)r0 * NR + col) = make_float2(v0, v1);
                if (r1 < M) *(float2*)(of + (size_t)r1 * NR + col) = make_float2(v2, v3);
            }
        }
    }
}

// ---------------- launch ----------------
extern "C" void kernel_launch(void* const* d_in, const int* in_sizes, int n_in,
                              void* d_out, int out_size) {
    const float* x   = (const float*)d_in[0];
    const int*   src = (const int*)d_in[1];
    const int*   dst = (const int*)d_in[2];
    const float* W1  = (const float*)d_in[3];
    const float* b1  = (const float*)d_in[4];
    const float* W2  = (const float*)d_in[5];
    const float* b2  = (const float*)d_in[6];
    const float* Wm1 = (const float*)d_in[7];
    const float* bm1 = (const float*)d_in[8];
    const float* Wm2 = (const float*)d_in[9];
    const float* bm2 = (const float*)d_in[10];
    float* out = (float*)d_out;

    void *p_xb, *p_aggb, *p_hb, *p_mb, *p_w1t, *p_w2t, *p_wm1t, *p_wm2t, *p_outnorm;
    cudaGetSymbolAddress(&p_xb, g_xb);
    cudaGetSymbolAddress(&p_aggb, g_aggb);
    cudaGetSymbolAddress(&p_hb, g_hb);
    cudaGetSymbolAddress(&p_mb, g_mb);
    cudaGetSymbolAddress(&p_w1t, g_w1t);
    cudaGetSymbolAddress(&p_w2t, g_w2t);
    cudaGetSymbolAddress(&p_wm1t, g_wm1t);
    cudaGetSymbolAddress(&p_wm2t, g_wm2t);
    cudaGetSymbolAddress(&p_outnorm, g_outnorm);

    // smem: A 128*136*2 + B NR*136*2 + bias NR*4
    constexpr int SMEM_G128 = 128 * 136 * 2 + 128 * 136 * 2 + 512;  // 70144
    constexpr int SMEM_G64  = 128 * 136 * 2 + 64 * 136 * 2 + 256;   // 52480
    cudaFuncSetAttribute(mma_gemm_kernel<128, 0, true, true>,
                         cudaFuncAttributeMaxDynamicSharedMemorySize, SMEM_G128);
    cudaFuncSetAttribute(mma_gemm_kernel<128, 0, true, false>,
                         cudaFuncAttributeMaxDynamicSharedMemorySize, SMEM_G128);
    cudaFuncSetAttribute(mma_gemm_kernel<64, 2, false, false>,
                         cudaFuncAttributeMaxDynamicSharedMemorySize, SMEM_G64);

    const int TB = 256;
    int nblk = (NN + TB - 1) / TB;
    int eblk = (EE + TB - 1) / TB;
    int sblk = (NN + 1023) / 1024;  // 98
    int gblk = (NN + 127) / 128;    // 782

    // graph preprocessing
    zero_kernel<<<nblk, TB>>>();
    degree_kernel<<<eblk, TB>>>(src, dst);
    scan_reduce_kernel<<<sblk, 256>>>();
    scan_partials_kernel<<<1, 128>>>(sblk);
    scan_down_kernel<<<sblk, 1024>>>();
    fill_kernel<<<eblk, TB>>>(src, dst);

    // dtype prep
    tobf16_kernel<<<(NN * 32 + TB - 1) / TB, TB>>>((const float4*)x);
    wt_kernel<<<(57344 + TB - 1) / TB, TB>>>(W1, W2, Wm1, Wm2);

    int ablk = (NN * 32 + TB - 1) / TB;

    // conv1: agg (x * outnorm[src], * innorm[dst]) -> aggb; GEMM1 -> xb (relu * outnorm, bf16)
    agg_kernel<true><<<ablk, TB>>>();
    mma_gemm_kernel<128, 0, true, true><<<gblk, 256, SMEM_G128>>>(
        (const __nv_bfloat16*)p_aggb, (const __nv_bfloat16*)p_w1t, b1,
        (const float*)p_outnorm, p_xb, NN);

    // conv2
    agg_kernel<false><<<ablk, TB>>>();
    mma_gemm_kernel<128, 0, true, false><<<gblk, 256, SMEM_G128>>>(
        (const __nv_bfloat16*)p_aggb, (const __nv_bfloat16*)p_w2t, b2,
        nullptr, p_hb, NN);

    // MLP head
    mma_gemm_kernel<128, 0, true, false><<<gblk, 256, SMEM_G128>>>(
        (const __nv_bfloat16*)p_hb, (const __nv_bfloat16*)p_wm1t, bm1,
        nullptr, p_mb, NN);
    mma_gemm_kernel<64, 2, false, false><<<gblk, 256, SMEM_G64>>>(
        (const __nv_bfloat16*)p_mb, (const __nv_bfloat16*)p_wm2t, bm2,
        nullptr, out, NN);
}